// round 5
// baseline (speedup 1.0000x reference)
#include <cuda_runtime.h>
#include <cstdint>

#define BM 128
#define BN 128
#define BK 16
#define R_TOTAL 120087
#define OUT_C 84

// Scratch: concatenated per-level (2,256,H,W) tensors. 512 * 13343 floats each.
__device__ float g_bufA[512 * 13343];
__device__ float g_bufB[512 * 13343];

struct ConvArgs {
    const float* in[5];    // per-level input base (each is (2,256,HW) contiguous)
    float* outp[5];        // per-level output base (mode 0) or d_out (mode 1/2)
    int row_off[5];        // row offset into (N,R,84) output for mode 1/2
    int Hs[5];
    int tile_off[6];       // cumulative pixel-tile offsets per level
    int Cout;
    int mode;              // 0 = tower conv (+ReLU, NCHW out); 1 = cls final; 2 = box final
};

__device__ __forceinline__ unsigned long long pack2(float lo, float hi) {
    unsigned long long r;
    asm("mov.b64 %0, {%1, %2};" : "=l"(r) : "f"(lo), "f"(hi));
    return r;
}
__device__ __forceinline__ void unpack2(unsigned long long v, float& lo, float& hi) {
    asm("mov.b64 {%0, %1}, %2;" : "=f"(lo), "=f"(hi) : "l"(v));
}
__device__ __forceinline__ void fma2(unsigned long long& d, unsigned long long a,
                                     unsigned long long b) {
    asm("fma.rn.f32x2 %0, %1, %2, %0;" : "+l"(d) : "l"(a), "l"(b));
}

__global__ __launch_bounds__(256, 2)
void conv_gemm_kernel(ConvArgs args, const float* __restrict__ wgt,
                      const float* __restrict__ bias)
{
    // ---- level lookup from pixel-tile id ----
    const int t = blockIdx.x;
    int l = 0;
#pragma unroll
    for (int i = 1; i < 5; ++i) l = (t >= args.tile_off[i]) ? i : l;

    const int H = args.Hs[l];
    const int W = H;
    const int HW = H * W;
    const int Cout = args.Cout;
    const int mode = args.mode;
    const int Kdim = 2304;          // 256 * 9
    const int numK = Kdim / BK;     // 144

    const int n  = blockIdx.z;
    const int m0 = blockIdx.y * BM;
    const int p0 = (t - args.tile_off[l]) * BN;
    const float* in_n = args.in[l] + (size_t)(n * 256) * HW;

    __shared__ __align__(16) float As[2][BK][BM + 4];
    __shared__ __align__(16) float Bs[2][BK][BN];

    const int tid = threadIdx.x;
    // B-tile load mapping: column pp fixed per thread, 8 k-rows per thread
    const int pp = tid & (BN - 1);
    const int kr = tid >> 7;              // 0 or 1
    const int p  = p0 + pp;
    const bool pv = p < HW;
    const int py = pv ? (p / W) : 0;
    const int px = pv ? (p - py * W) : 0;

    // compute-thread mapping
    const int tm = tid >> 4;              // 0..15 -> output rows tm*8..
    const int tn = tid & 15;              // 0..15 -> output cols tn*8..

    unsigned long long acc2[8][4];
#pragma unroll
    for (int i = 0; i < 8; ++i)
#pragma unroll
        for (int j = 0; j < 4; ++j) acc2[i][j] = 0ULL;

    float breg[8];
    float4 areg[2];

    // ---------------- prologue: load K-block 0 into stage 0 ----------------
    {
        const int k0 = 0;
#pragma unroll
        for (int i = 0; i < 8; ++i) {
            int k   = k0 + kr + 2 * i;
            int ci  = k / 9;
            int rem = k - ci * 9;
            int ky  = rem / 3;
            int kx  = rem - ky * 3;
            int iy  = py + ky - 1;
            int ix  = px + kx - 1;
            bool ok = pv && ((unsigned)iy < (unsigned)H) && ((unsigned)ix < (unsigned)W);
            breg[i] = ok ? __ldg(in_n + (size_t)ci * HW + iy * W + ix) : 0.f;
        }
#pragma unroll
        for (int j = 0; j < 2; ++j) {
            int idx4 = tid + j * 256;
            int m    = idx4 >> 2;
            int kv   = (idx4 & 3) * 4;
            int co   = m0 + m;
            areg[j] = (co < Cout)
                ? *reinterpret_cast<const float4*>(wgt + (size_t)co * Kdim + k0 + kv)
                : make_float4(0.f, 0.f, 0.f, 0.f);
        }
#pragma unroll
        for (int i = 0; i < 8; ++i) Bs[0][kr + 2 * i][pp] = breg[i];
#pragma unroll
        for (int j = 0; j < 2; ++j) {
            int idx4 = tid + j * 256;
            int m    = idx4 >> 2;
            int kv   = (idx4 & 3) * 4;
            As[0][kv + 0][m] = areg[j].x;
            As[0][kv + 1][m] = areg[j].y;
            As[0][kv + 2][m] = areg[j].z;
            As[0][kv + 3][m] = areg[j].w;
        }
    }
    __syncthreads();

    // ---------------- main loop: prefetch(kb+1) | compute(kb) | store ----------------
    for (int kb = 0; kb < numK; ++kb) {
        const int cur = kb & 1;
        const bool has_next = (kb + 1 < numK);

        if (has_next) {
            const int k0 = (kb + 1) * BK;
#pragma unroll
            for (int i = 0; i < 8; ++i) {
                int k   = k0 + kr + 2 * i;
                int ci  = k / 9;
                int rem = k - ci * 9;
                int ky  = rem / 3;
                int kx  = rem - ky * 3;
                int iy  = py + ky - 1;
                int ix  = px + kx - 1;
                bool ok = pv && ((unsigned)iy < (unsigned)H) && ((unsigned)ix < (unsigned)W);
                breg[i] = ok ? __ldg(in_n + (size_t)ci * HW + iy * W + ix) : 0.f;
            }
#pragma unroll
            for (int j = 0; j < 2; ++j) {
                int idx4 = tid + j * 256;
                int m    = idx4 >> 2;
                int kv   = (idx4 & 3) * 4;
                int co   = m0 + m;
                areg[j] = (co < Cout)
                    ? *reinterpret_cast<const float4*>(wgt + (size_t)co * Kdim + k0 + kv)
                    : make_float4(0.f, 0.f, 0.f, 0.f);
            }
        }

        const float* Ab = &As[cur][0][0];
        const float* Bb = &Bs[cur][0][0];
#pragma unroll
        for (int kk = 0; kk < BK; ++kk) {
            float4 a0 = *reinterpret_cast<const float4*>(Ab + kk * (BM + 4) + tm * 8);
            float4 a1 = *reinterpret_cast<const float4*>(Ab + kk * (BM + 4) + tm * 8 + 4);
            float4 b0 = *reinterpret_cast<const float4*>(Bb + kk * BN + tn * 8);
            float4 b1 = *reinterpret_cast<const float4*>(Bb + kk * BN + tn * 8 + 4);
            float av[8] = {a0.x, a0.y, a0.z, a0.w, a1.x, a1.y, a1.z, a1.w};
            unsigned long long bp[4] = {pack2(b0.x, b0.y), pack2(b0.z, b0.w),
                                        pack2(b1.x, b1.y), pack2(b1.z, b1.w)};
#pragma unroll
            for (int i = 0; i < 8; ++i) {
                unsigned long long a2 = pack2(av[i], av[i]);
#pragma unroll
                for (int j = 0; j < 4; ++j) fma2(acc2[i][j], a2, bp[j]);
            }
        }

        if (has_next) {
            const int st = cur ^ 1;
#pragma unroll
            for (int i = 0; i < 8; ++i) Bs[st][kr + 2 * i][pp] = breg[i];
#pragma unroll
            for (int j = 0; j < 2; ++j) {
                int idx4 = tid + j * 256;
                int m    = idx4 >> 2;
                int kv   = (idx4 & 3) * 4;
                As[st][kv + 0][m] = areg[j].x;
                As[st][kv + 1][m] = areg[j].y;
                As[st][kv + 2][m] = areg[j].z;
                As[st][kv + 3][m] = areg[j].w;
            }
        }
        __syncthreads();
    }

    // ---------------- epilogue ----------------
#pragma unroll
    for (int i = 0; i < 8; ++i) {
        int co = m0 + tm * 8 + i;
        if (co >= Cout) continue;
        float bb = __ldg(bias + co);
        float vals[8];
#pragma unroll
        for (int j = 0; j < 4; ++j) unpack2(acc2[i][j], vals[2 * j], vals[2 * j + 1]);
#pragma unroll
        for (int j = 0; j < 8; ++j) {
            int pc = p0 + tn * 8 + j;
            if (pc >= HW) continue;
            float v = vals[j] + bb;
            if (mode == 0) {
                args.outp[l][((size_t)(n * 256) + co) * HW + pc] = fmaxf(v, 0.f);
            } else if (mode == 1) {
                int a  = co / 80;
                int kc = co - a * 80;
                size_t r = (size_t)args.row_off[l] + (size_t)pc * 9 + a;
                args.outp[l][((size_t)n * R_TOTAL + r) * OUT_C + kc] = v;
            } else {
                int a  = co >> 2;
                int jb = co & 3;
                size_t r = (size_t)args.row_off[l] + (size_t)pc * 9 + a;
                args.outp[l][((size_t)n * R_TOTAL + r) * OUT_C + 80 + jb] = v;
            }
        }
    }
}

// ---------------------------------------------------------------------------
static const int HS[5]      = {100, 50, 25, 13, 7};
static const int CUMHW[5]   = {0, 10000, 12500, 13125, 13294};
static const int ROWOFF[5]  = {0, 90000, 112500, 118125, 119646};
static const int TILEOFF[6] = {0, 79, 99, 104, 106, 107};

extern "C" void kernel_launch(void* const* d_in, const int* in_sizes, int n_in,
                              void* d_out, int out_size)
{
    float* bufA = nullptr;
    float* bufB = nullptr;
    cudaGetSymbolAddress((void**)&bufA, g_bufA);
    cudaGetSymbolAddress((void**)&bufB, g_bufB);
    float* out = (float*)d_out;

    ConvArgs base;
    for (int i = 0; i < 6; ++i) base.tile_off[i] = TILEOFF[i];
    for (int lv = 0; lv < 5; ++lv) {
        base.Hs[lv]      = HS[lv];
        base.row_off[lv] = ROWOFF[lv];
    }

    auto set_in_buf = [&](ConvArgs& a, float* buf) {
        for (int lv = 0; lv < 5; ++lv) a.in[lv] = buf + (size_t)512 * CUMHW[lv];
    };
    auto set_out_buf = [&](ConvArgs& a, float* buf) {
        for (int lv = 0; lv < 5; ++lv) a.outp[lv] = buf + (size_t)512 * CUMHW[lv];
    };
    auto launch = [&](const ConvArgs& a, const float* w, const float* b) {
        dim3 grid(TILEOFF[5], (a.Cout + BM - 1) / BM, 2);
        conv_gemm_kernel<<<grid, 256>>>(a, w, b);
    };

    float* bufs[2] = {bufA, bufB};

    for (int tower = 0; tower < 2; ++tower) {
        const int wbase = 5 + tower * 8;

        // layer 0: input = FPN features f0..f4
        ConvArgs a0 = base;
        a0.Cout = 256; a0.mode = 0;
        for (int lv = 0; lv < 5; ++lv) a0.in[lv] = (const float*)d_in[lv];
        set_out_buf(a0, bufs[0]);
        launch(a0, (const float*)d_in[wbase + 0], (const float*)d_in[wbase + 1]);

        // layers 1..3 ping-pong: A -> B -> A -> B
        for (int i = 1; i < 4; ++i) {
            ConvArgs ai = base;
            ai.Cout = 256; ai.mode = 0;
            set_in_buf(ai, bufs[(i + 1) & 1]);
            set_out_buf(ai, bufs[i & 1]);
            launch(ai, (const float*)d_in[wbase + 2 * i],
                       (const float*)d_in[wbase + 2 * i + 1]);
        }

        // final head conv: reads bufB, writes permuted directly into d_out
        ConvArgs af = base;
        set_in_buf(af, bufs[1]);
        for (int lv = 0; lv < 5; ++lv) af.outp[lv] = out;
        if (tower == 0) {
            af.Cout = 720; af.mode = 1;   // cls logits -> columns [0,80)
            launch(af, (const float*)d_in[21], (const float*)d_in[22]);
        } else {
            af.Cout = 36;  af.mode = 2;   // box deltas -> columns [80,84)
            launch(af, (const float*)d_in[23], (const float*)d_in[24]);
        }
    }
}

// round 11
// speedup vs baseline: 3.2604x; 3.2604x over previous
#include <cuda_runtime.h>
#include <cstdint>

#define BM 128
#define BN 256
#define R_TOTAL 120087
#define OUT_C 84
#define KCHUNKS 72
#define ASTAGE 16384            // 128 rows x 32 k x 4B, fragment-packed
#define BSTAGE 36864            // 256 rows x 36 floats (stride pad) x 4B
#define SMEM_BYTES 212992       // 4*ASTAGE + 4*BSTAGE

// ---------------- device scratch ----------------
__device__ float g_bufIn[6831616];   // NHWC input (2,HW,256) concat levels (tf32-rounded)
__device__ float g_bufA [6831616];
__device__ float g_bufB [6831616];
__device__ float g_wpack[6782976];   // 23 row-blocks * 72 chunks * 4096 floats, frag-packed

// ---------------- PTX helpers ----------------
__device__ __forceinline__ uint32_t smem_u32(const void* p) {
    uint32_t a;
    asm("{ .reg .u64 t; cvta.to.shared.u64 t, %1; cvt.u32.u64 %0, t; }" : "=r"(a) : "l"(p));
    return a;
}
__device__ __forceinline__ void cp16_cg(uint32_t dst, const float* src, uint32_t sz) {
    asm volatile("cp.async.cg.shared.global [%0], [%1], 16, %2;" :: "r"(dst), "l"(src), "r"(sz) : "memory");
}
__device__ __forceinline__ void cp_commit() { asm volatile("cp.async.commit_group;" ::: "memory"); }
__device__ __forceinline__ void cp_wait3()  { asm volatile("cp.async.wait_group 3;"  ::: "memory"); }

__device__ __forceinline__ float tf32r(float x) {
    uint32_t u;
    asm("cvt.rna.tf32.f32 %0, %1;" : "=r"(u) : "f"(x));
    return __uint_as_float(u);
}

__device__ __forceinline__ void mma_tf32(float& d0, float& d1, float& d2, float& d3,
                                         uint32_t a0, uint32_t a1, uint32_t a2, uint32_t a3,
                                         uint32_t b0, uint32_t b1) {
    asm volatile("mma.sync.aligned.m16n8k8.row.col.f32.tf32.tf32.f32 "
                 "{%0,%1,%2,%3}, {%4,%5,%6,%7}, {%8,%9}, {%0,%1,%2,%3};"
                 : "+f"(d0), "+f"(d1), "+f"(d2), "+f"(d3)
                 : "r"(a0), "r"(a1), "r"(a2), "r"(a3), "r"(b0), "r"(b1));
}

// ---------------- arg structs ----------------
struct ConvArgs {
    const float* in[5];      // NHWC level bases [n][p][256]
    float* outp[5];          // NHWC bases (mode 0) or d_out (mode 1/2)
    const float* wgt;        // fragment-packed weights base for this conv
    const float* bias;
    int row_off[5];
    int Hs[5];
    int tile_off[6];
    int Cout;
    int mode;                // 0 tower(+relu,tf32 round), 1 cls head, 2 box head
};
struct TransArgs { const float* in[5]; float* out[5]; int Hs[5]; int toff[6]; };
struct WPArgs { const float* src[10]; int mbcum[11]; int cout[10]; };

// ---------------- prepass: NCHW -> NHWC with tf32 rounding ----------------
__global__ void nchw2nhwc(TransArgs a) {
    __shared__ float tile[32][33];
    int t = blockIdx.x;
    int l = 0;
#pragma unroll
    for (int i = 1; i < 5; ++i) l = (t >= a.toff[i]) ? i : l;
    const int HW = a.Hs[l] * a.Hs[l];
    const int p0 = (t - a.toff[l]) * 32;
    const int c0 = blockIdx.y * 32;
    const int n  = blockIdx.z;
    const float* src = a.in[l]  + (size_t)n * 256 * HW;
    float*       dst = a.out[l] + (size_t)n * HW * 256;
    const int tx = threadIdx.x, ty = threadIdx.y;
#pragma unroll
    for (int i = 0; i < 4; ++i) {
        int cc = ty + 8 * i;
        int p  = p0 + tx;
        tile[cc][tx] = (p < HW) ? src[(size_t)(c0 + cc) * HW + p] : 0.f;
    }
    __syncthreads();
#pragma unroll
    for (int i = 0; i < 4; ++i) {
        int pp = ty + 8 * i;
        int p  = p0 + pp;
        if (p < HW) dst[(size_t)p * 256 + c0 + tx] = tf32r(tile[tx][pp]);
    }
}

// ---------------- prepass: weight fragment packing ----------------
// src weight (Cout, 256, 3, 3) row-major; k' = tap*256 + ci; chunk c = k'>>5.
// Packed page (rb, c): 4096 floats, layout:
//   idx = (((wm*4+mt)*4+ks)*32 + g*4+tig)*4 + (i + 2*j)
// for element (m = wm*64+mt*16+8*i+g, k = ks*8+4*j+tig).
__global__ void wpack_kernel(WPArgs a, float* __restrict__ dst) {
    const int c  = blockIdx.x;
    const int rb = blockIdx.y;
    int t = 0;
#pragma unroll
    for (int i = 1; i < 10; ++i) if (rb >= a.mbcum[i]) t = i;
    const int rbl = rb - a.mbcum[t];
    const float* w = a.src[t];
    const int Cout = a.cout[t];
    float* page = dst + ((size_t)rb * KCHUNKS + c) * 4096;

    for (int idx = threadIdx.x; idx < 4096; idx += 256) {
        const int m = idx >> 5;
        const int k = idx & 31;
        const int co = rbl * 128 + m;
        float v = 0.f;
        if (co < Cout) {
            const int kp  = c * 32 + k;
            const int tap = kp >> 8;
            const int ci  = kp & 255;
            v = tf32r(w[(size_t)co * 2304 + ci * 9 + tap]);
        }
        const int wm = m >> 6, mt = (m >> 4) & 3, g = m & 7, i2 = (m >> 3) & 1;
        const int ks = k >> 3, tig = k & 3, j = (k >> 2) & 1;
        page[((((wm * 4 + mt) * 4 + ks) * 32 + g * 4 + tig) << 2) + i2 + 2 * j] = v;
    }
}

// ---------------- main tensor-core conv kernel ----------------
__global__ __launch_bounds__(256, 1)
void conv_mma_kernel(ConvArgs args)
{
    extern __shared__ __align__(1024) char smem[];
    const uint32_t sbase = smem_u32(smem);
    const int tid  = threadIdx.x;
    const int wid  = tid >> 5;
    const int lane = tid & 31;
    const int g    = lane >> 2;
    const int tig  = lane & 3;
    const int wm   = wid & 1;     // m half: 0/1 -> co [0,64)/[64,128)
    const int wn   = wid >> 1;    // n quarter: 0..3 -> px 64-slices

    // level lookup
    const int t = blockIdx.x;
    int l = 0;
#pragma unroll
    for (int i = 1; i < 5; ++i) l = (t >= args.tile_off[i]) ? i : l;
    const int H = args.Hs[l], W = H, HW = H * W;
    const int n  = blockIdx.z;
    const int m0 = blockIdx.y * BM;
    const int p0 = (t - args.tile_off[l]) * BN;
    const float* in_n  = args.in[l] + (size_t)n * HW * 256;
    const float* apack = args.wgt + (size_t)blockIdx.y * KCHUNKS * 4096;

    // producer mapping for B: 8 rows per thread
    const int rB = tid >> 3;           // base row 0..31
    const int tt = tid & 7;            // 16B chunk in 128B row
    int py[8], px[8];
    bool pv[8];
#pragma unroll
    for (int j = 0; j < 8; ++j) {
        int p = p0 + rB + 32 * j;
        pv[j] = p < HW;
        py[j] = pv[j] ? p / W : 0;
        px[j] = pv[j] ? p - py[j] * W : 0;
    }

    auto fill = [&](int c) {
        const int st = c & 3;
        const uint32_t abase = sbase + st * ASTAGE;
        const uint32_t bbase = sbase + 4 * ASTAGE + st * BSTAGE;
        // A: linear coalesced copy of fragment-packed page
        const float* ap = apack + (size_t)c * 4096;
#pragma unroll
        for (int j = 0; j < 4; ++j)
            cp16_cg(abase + (tid + 256 * j) * 16, ap + (tid + 256 * j) * 4, 16);
        // B: NHWC gather with halo zero-fill
        const int slice = c >> 3;
        const int dy = slice / 3 - 1;
        const int dx = slice - (slice / 3) * 3 - 1;
        const int cc = (c & 7) << 5;
#pragma unroll
        for (int j = 0; j < 8; ++j) {
            const int r  = rB + 32 * j;
            const int iy = py[j] + dy, ix = px[j] + dx;
            const bool ok = pv[j] && ((unsigned)iy < (unsigned)H) && ((unsigned)ix < (unsigned)W);
            const float* bsrc = ok ? (in_n + (((size_t)iy * W + ix) << 8) + cc + tt * 4) : in_n;
            cp16_cg(bbase + r * 144 + tt * 16, bsrc, ok ? 16u : 0u);
        }
    };

    float d[4][8][4];
#pragma unroll
    for (int mt = 0; mt < 4; ++mt)
#pragma unroll
        for (int nt = 0; nt < 8; ++nt)
#pragma unroll
            for (int q = 0; q < 4; ++q) d[mt][nt][q] = 0.f;

    fill(0); cp_commit();
    fill(1); cp_commit();
    fill(2); cp_commit();

    for (int c = 0; c < KCHUNKS; ++c) {
        if (c + 3 < KCHUNKS) fill(c + 3);
        cp_commit();
        cp_wait3();
        __syncthreads();

        const uint4*    Af = (const uint4*)(smem + (c & 3) * ASTAGE);
        const uint32_t* Bf = (const uint32_t*)(smem + 4 * ASTAGE + (c & 3) * BSTAGE);
#pragma unroll
        for (int ks = 0; ks < 4; ++ks) {
            uint4 a[4];
#pragma unroll
            for (int mt = 0; mt < 4; ++mt)
                a[mt] = Af[((wm * 4 + mt) * 4 + ks) * 32 + lane];
            uint32_t b[8][2];
#pragma unroll
            for (int nt = 0; nt < 8; ++nt) {
                const int nn = (wn * 64 + nt * 8 + g) * 36 + ks * 8 + tig;
                b[nt][0] = Bf[nn];
                b[nt][1] = Bf[nn + 4];
            }
#pragma unroll
            for (int mt = 0; mt < 4; ++mt)
#pragma unroll
                for (int nt = 0; nt < 8; ++nt)
                    mma_tf32(d[mt][nt][0], d[mt][nt][1], d[mt][nt][2], d[mt][nt][3],
                             a[mt].x, a[mt].y, a[mt].z, a[mt].w, b[nt][0], b[nt][1]);
        }
        __syncthreads();
    }

    // ---------------- epilogue: stage warp tile in smem, coalesced stores ----
    float* S = (float*)smem + wid * 64 * 68;   // [n=64][m=64], stride 68 (16B-aligned rows)
#pragma unroll
    for (int mt = 0; mt < 4; ++mt)
#pragma unroll
        for (int nt = 0; nt < 8; ++nt) {
            const int mb = mt * 16 + g;
            const int nb = nt * 8 + tig * 2;
            S[(nb + 0) * 68 + mb]     = d[mt][nt][0];
            S[(nb + 1) * 68 + mb]     = d[mt][nt][1];
            S[(nb + 0) * 68 + mb + 8] = d[mt][nt][2];
            S[(nb + 1) * 68 + mb + 8] = d[mt][nt][3];
        }
    __syncwarp();

    const int q    = lane & 15;
    const int half = lane >> 4;
    const int co0  = m0 + wm * 64;
    const int pw0  = p0 + wn * 64;
    const int Cout = args.Cout;
    const int mode = args.mode;

    if (mode == 0) {
        float4 b4 = *(const float4*)(args.bias + co0 + q * 4);
        float* ob = args.outp[l] + (size_t)n * HW * 256;
#pragma unroll 4
        for (int it = 0; it < 32; ++it) {
            const int row = it * 2 + half;
            const int p   = pw0 + row;
            if (p >= HW) continue;
            float4 v = *(const float4*)&S[row * 68 + q * 4];
            v.x = tf32r(fmaxf(v.x + b4.x, 0.f));
            v.y = tf32r(fmaxf(v.y + b4.y, 0.f));
            v.z = tf32r(fmaxf(v.z + b4.z, 0.f));
            v.w = tf32r(fmaxf(v.w + b4.w, 0.f));
            *(float4*)(ob + (size_t)p * 256 + co0 + q * 4) = v;
        }
    } else {
        float bb[4];
        int   cos[4];
#pragma unroll
        for (int e = 0; e < 4; ++e) {
            cos[e] = co0 + q * 4 + e;
            bb[e]  = (cos[e] < Cout) ? __ldg(args.bias + cos[e]) : 0.f;
        }
        float* ob = args.outp[l];
        const size_t nbase = (size_t)n * R_TOTAL + args.row_off[l];
#pragma unroll 2
        for (int it = 0; it < 32; ++it) {
            const int row = it * 2 + half;
            const int p   = pw0 + row;
            if (p >= HW) continue;
            float4 v = *(const float4*)&S[row * 68 + q * 4];
            float vv[4] = {v.x, v.y, v.z, v.w};
#pragma unroll
            for (int e = 0; e < 4; ++e) {
                const int co = cos[e];
                if (co >= Cout) continue;
                if (mode == 1) {
                    const int a  = co / 80;
                    const int kc = co - a * 80;
                    ob[(nbase + (size_t)p * 9 + a) * OUT_C + kc] = vv[e] + bb[e];
                } else {
                    const int a  = co >> 2;
                    const int jb = co & 3;
                    ob[(nbase + (size_t)p * 9 + a) * OUT_C + 80 + jb] = vv[e] + bb[e];
                }
            }
        }
    }
}

// ---------------- host ----------------
static const int HS[5]      = {100, 50, 25, 13, 7};
static const int CUMHW[5]   = {0, 10000, 12500, 13125, 13294};
static const int ROWOFF[5]  = {0, 90000, 112500, 118125, 119646};
static const int TILEOFF[6] = {0, 40, 50, 53, 54, 55};     // 256-px tiles
static const int T32OFF[6]  = {0, 313, 392, 412, 418, 420}; // 32-px tiles (transpose)
// conv order: cls0..3, clsHead, box0..3, boxHead ; m-blocks: 2,2,2,2,6,2,2,2,2,1
static const int MBCUM[11]  = {0, 2, 4, 6, 8, 14, 16, 18, 20, 22, 23};
static const int WSRC[10]   = {5, 7, 9, 11, 21, 13, 15, 17, 19, 23};
static const int WCOUT[10]  = {256, 256, 256, 256, 720, 256, 256, 256, 256, 36};

extern "C" void kernel_launch(void* const* d_in, const int* in_sizes, int n_in,
                              void* d_out, int out_size)
{
    float *bufIn = nullptr, *bufA = nullptr, *bufB = nullptr, *wpk = nullptr;
    cudaGetSymbolAddress((void**)&bufIn, g_bufIn);
    cudaGetSymbolAddress((void**)&bufA,  g_bufA);
    cudaGetSymbolAddress((void**)&bufB,  g_bufB);
    cudaGetSymbolAddress((void**)&wpk,   g_wpack);
    float* out = (float*)d_out;

    cudaFuncSetAttribute(conv_mma_kernel, cudaFuncAttributeMaxDynamicSharedMemorySize, SMEM_BYTES);

    // 1) NCHW -> NHWC (+ tf32 rounding)
    {
        TransArgs ta;
        for (int lv = 0; lv < 5; ++lv) {
            ta.in[lv]  = (const float*)d_in[lv];
            ta.out[lv] = bufIn + (size_t)512 * CUMHW[lv];
            ta.Hs[lv]  = HS[lv];
        }
        for (int i = 0; i < 6; ++i) ta.toff[i] = T32OFF[i];
        nchw2nhwc<<<dim3(420, 8, 2), dim3(32, 8)>>>(ta);
    }

    // 2) weight fragment packing (+ tf32 rounding + row-block zero padding)
    {
        WPArgs wa;
        for (int i = 0; i < 10; ++i) { wa.src[i] = (const float*)d_in[WSRC[i]]; wa.cout[i] = WCOUT[i]; }
        for (int i = 0; i < 11; ++i) wa.mbcum[i] = MBCUM[i];
        wpack_kernel<<<dim3(KCHUNKS, 23), 256>>>(wa, wpk);
    }

    ConvArgs base;
    for (int i = 0; i < 6; ++i) base.tile_off[i] = TILEOFF[i];
    for (int lv = 0; lv < 5; ++lv) {
        base.Hs[lv]      = HS[lv];
        base.row_off[lv] = ROWOFF[lv];
    }
    auto set_in  = [&](ConvArgs& a, float* buf) {
        for (int lv = 0; lv < 5; ++lv) a.in[lv] = buf + (size_t)512 * CUMHW[lv];
    };
    auto set_out = [&](ConvArgs& a, float* buf) {
        for (int lv = 0; lv < 5; ++lv) a.outp[lv] = buf + (size_t)512 * CUMHW[lv];
    };
    auto launch = [&](const ConvArgs& a, int conv) {
        const int mblocks = MBCUM[conv + 1] - MBCUM[conv];
        dim3 grid(TILEOFF[5], mblocks, 2);
        conv_mma_kernel<<<grid, 256, SMEM_BYTES>>>(a);
    };

    float* bufs[2] = {bufA, bufB};

    for (int tower = 0; tower < 2; ++tower) {
        const int conv0   = (tower == 0) ? 0 : 5;
        const int biasIdx = (tower == 0) ? 6 : 14;   // tower biases stride 2

        for (int i = 0; i < 4; ++i) {
            ConvArgs ai = base;
            ai.Cout = 256; ai.mode = 0;
            ai.wgt  = wpk + (size_t)MBCUM[conv0 + i] * KCHUNKS * 4096;
            ai.bias = (const float*)d_in[biasIdx + 2 * i];
            if (i == 0) set_in(ai, bufIn);
            else        set_in(ai, bufs[(i + 1) & 1]);
            set_out(ai, bufs[i & 1]);
            launch(ai, conv0 + i);
        }

        ConvArgs af = base;
        set_in(af, bufs[1]);
        for (int lv = 0; lv < 5; ++lv) af.outp[lv] = out;
        const int hconv = (tower == 0) ? 4 : 9;
        af.wgt = wpk + (size_t)MBCUM[hconv] * KCHUNKS * 4096;
        if (tower == 0) { af.Cout = 720; af.mode = 1; af.bias = (const float*)d_in[22]; }
        else            { af.Cout = 36;  af.mode = 2; af.bias = (const float*)d_in[24]; }
        launch(af, hconv);
    }
}

// round 12
// speedup vs baseline: 3.5496x; 1.0887x over previous
#include <cuda_runtime.h>
#include <cstdint>

#define BM 128
#define BN 192
#define NTHREADS 384
#define R_TOTAL 120087
#define OUT_C 84
#define KCHUNKS 72
#define ASTAGE 16384            // 128 rows x 32 k x 4B, fragment-packed
#define BSTAGE 27648            // 192 rows x 36 floats (stride pad) x 4B
#define SMEM_BYTES 176128       // 4*(ASTAGE + BSTAGE)

// ---------------- device scratch ----------------
__device__ float g_bufIn[6831616];   // NHWC input (2,HW,256) concat levels (tf32-rounded)
__device__ float g_bufA [6831616];
__device__ float g_bufB [6831616];
__device__ float g_wpack[6782976];   // 23 row-blocks * 72 chunks * 4096 floats, frag-packed

// ---------------- PTX helpers ----------------
__device__ __forceinline__ uint32_t smem_u32(const void* p) {
    uint32_t a;
    asm("{ .reg .u64 t; cvta.to.shared.u64 t, %1; cvt.u32.u64 %0, t; }" : "=r"(a) : "l"(p));
    return a;
}
__device__ __forceinline__ void cp16_cg(uint32_t dst, const float* src, uint32_t sz) {
    asm volatile("cp.async.cg.shared.global [%0], [%1], 16, %2;" :: "r"(dst), "l"(src), "r"(sz) : "memory");
}
__device__ __forceinline__ void cp_commit() { asm volatile("cp.async.commit_group;" ::: "memory"); }
__device__ __forceinline__ void cp_wait3()  { asm volatile("cp.async.wait_group 3;"  ::: "memory"); }

__device__ __forceinline__ float tf32r(float x) {
    uint32_t u;
    asm("cvt.rna.tf32.f32 %0, %1;" : "=r"(u) : "f"(x));
    return __uint_as_float(u);
}

__device__ __forceinline__ void mma_tf32(float& d0, float& d1, float& d2, float& d3,
                                         uint32_t a0, uint32_t a1, uint32_t a2, uint32_t a3,
                                         uint32_t b0, uint32_t b1) {
    asm volatile("mma.sync.aligned.m16n8k8.row.col.f32.tf32.tf32.f32 "
                 "{%0,%1,%2,%3}, {%4,%5,%6,%7}, {%8,%9}, {%0,%1,%2,%3};"
                 : "+f"(d0), "+f"(d1), "+f"(d2), "+f"(d3)
                 : "r"(a0), "r"(a1), "r"(a2), "r"(a3), "r"(b0), "r"(b1));
}

// ---------------- arg structs ----------------
struct ConvArgs {
    const float* in[5];      // NHWC level bases [n][p][256]
    float* outp[5];          // NHWC bases (mode 0) or d_out (mode 1/2)
    const float* wgt;        // fragment-packed weights base for this conv
    const float* bias;
    int row_off[5];
    int Hs[5];
    int tile_off[6];
    int Cout;
    int mode;                // 0 tower(+relu,tf32 round), 1 cls head, 2 box head
};
struct TransArgs { const float* in[5]; float* out[5]; int Hs[5]; int toff[6]; };
struct WPArgs { const float* src[10]; int mbcum[11]; int cout[10]; };

// ---------------- prepass: NCHW -> NHWC with tf32 rounding ----------------
__global__ void nchw2nhwc(TransArgs a) {
    __shared__ float tile[32][33];
    int t = blockIdx.x;
    int l = 0;
#pragma unroll
    for (int i = 1; i < 5; ++i) l = (t >= a.toff[i]) ? i : l;
    const int HW = a.Hs[l] * a.Hs[l];
    const int p0 = (t - a.toff[l]) * 32;
    const int c0 = blockIdx.y * 32;
    const int n  = blockIdx.z;
    const float* src = a.in[l]  + (size_t)n * 256 * HW;
    float*       dst = a.out[l] + (size_t)n * HW * 256;
    const int tx = threadIdx.x, ty = threadIdx.y;
#pragma unroll
    for (int i = 0; i < 4; ++i) {
        int cc = ty + 8 * i;
        int p  = p0 + tx;
        tile[cc][tx] = (p < HW) ? src[(size_t)(c0 + cc) * HW + p] : 0.f;
    }
    __syncthreads();
#pragma unroll
    for (int i = 0; i < 4; ++i) {
        int pp = ty + 8 * i;
        int p  = p0 + pp;
        if (p < HW) dst[(size_t)p * 256 + c0 + tx] = tf32r(tile[tx][pp]);
    }
}

// ---------------- prepass: weight fragment packing ----------------
// src weight (Cout, 256, 3, 3) row-major; k' = tap*256 + ci; chunk c = k'>>5.
// Packed page (rb, c): 4096 floats, layout:
//   idx = (((wm*4+mt)*4+ks)*32 + g*4+tig)*4 + (i + 2*j)
// for element (m = wm*64+mt*16+8*i+g, k = ks*8+4*j+tig).
__global__ void wpack_kernel(WPArgs a, float* __restrict__ dst) {
    const int c  = blockIdx.x;
    const int rb = blockIdx.y;
    int t = 0;
#pragma unroll
    for (int i = 1; i < 10; ++i) if (rb >= a.mbcum[i]) t = i;
    const int rbl = rb - a.mbcum[t];
    const float* w = a.src[t];
    const int Cout = a.cout[t];
    float* page = dst + ((size_t)rb * KCHUNKS + c) * 4096;

    for (int idx = threadIdx.x; idx < 4096; idx += 256) {
        const int m = idx >> 5;
        const int k = idx & 31;
        const int co = rbl * 128 + m;
        float v = 0.f;
        if (co < Cout) {
            const int kp  = c * 32 + k;
            const int tap = kp >> 8;
            const int ci  = kp & 255;
            v = tf32r(w[(size_t)co * 2304 + ci * 9 + tap]);
        }
        const int wm = m >> 6, mt = (m >> 4) & 3, g = m & 7, i2 = (m >> 3) & 1;
        const int ks = k >> 3, tig = k & 3, j = (k >> 2) & 1;
        page[((((wm * 4 + mt) * 4 + ks) * 32 + g * 4 + tig) << 2) + i2 + 2 * j] = v;
    }
}

// ---------------- main tensor-core conv kernel ----------------
__global__ __launch_bounds__(NTHREADS, 1)
void conv_mma_kernel(ConvArgs args)
{
    extern __shared__ __align__(1024) char smem[];
    const uint32_t sbase = smem_u32(smem);
    const int tid  = threadIdx.x;
    const int wid  = tid >> 5;
    const int lane = tid & 31;
    const int g    = lane >> 2;
    const int tig  = lane & 3;
    const int wm   = wid & 1;     // m half: 0/1 -> co [0,64)/[64,128)
    const int wn   = wid >> 1;    // n slice: 0..5 -> px 32-slices

    // level lookup
    const int t = blockIdx.x;
    int l = 0;
#pragma unroll
    for (int i = 1; i < 5; ++i) l = (t >= args.tile_off[i]) ? i : l;
    const int H = args.Hs[l], W = H, HW = H * W;
    const int n  = blockIdx.z;
    const int m0 = blockIdx.y * BM;
    const int p0 = (t - args.tile_off[l]) * BN;
    const float* in_n  = args.in[l] + (size_t)n * HW * 256;
    const float* apack = args.wgt + (size_t)blockIdx.y * KCHUNKS * 4096;

    // producer mapping for B: 4 rows per thread (stride 48)
    const int rB = tid >> 3;           // base row 0..47
    const int tt = tid & 7;            // 16B chunk in 128B row
    int py[4], px[4];
    bool pv[4];
#pragma unroll
    for (int j = 0; j < 4; ++j) {
        int p = p0 + rB + 48 * j;
        pv[j] = p < HW;
        py[j] = pv[j] ? p / W : 0;
        px[j] = pv[j] ? p - py[j] * W : 0;
    }

    auto fill = [&](int c) {
        const int st = c & 3;
        const uint32_t abase = sbase + st * ASTAGE;
        const uint32_t bbase = sbase + 4 * ASTAGE + st * BSTAGE;
        // A: linear coalesced copy of fragment-packed page (1024 x 16B)
        const float* ap = apack + (size_t)c * 4096;
#pragma unroll
        for (int j = 0; j < 3; ++j) {
            const int idx = tid + NTHREADS * j;
            if (idx < 1024) cp16_cg(abase + idx * 16, ap + idx * 4, 16);
        }
        // B: NHWC gather with halo zero-fill
        const int slice = c >> 3;
        const int dy = slice / 3 - 1;
        const int dx = slice - (slice / 3) * 3 - 1;
        const int cc = (c & 7) << 5;
#pragma unroll
        for (int j = 0; j < 4; ++j) {
            const int r  = rB + 48 * j;
            const int iy = py[j] + dy, ix = px[j] + dx;
            const bool ok = pv[j] && ((unsigned)iy < (unsigned)H) && ((unsigned)ix < (unsigned)W);
            const float* bsrc = ok ? (in_n + (((size_t)iy * W + ix) << 8) + cc + tt * 4) : in_n;
            cp16_cg(bbase + r * 144 + tt * 16, bsrc, ok ? 16u : 0u);
        }
    };

    float d[4][4][4];
#pragma unroll
    for (int mt = 0; mt < 4; ++mt)
#pragma unroll
        for (int nt = 0; nt < 4; ++nt)
#pragma unroll
            for (int q = 0; q < 4; ++q) d[mt][nt][q] = 0.f;

    fill(0); cp_commit();
    fill(1); cp_commit();
    fill(2); cp_commit();

    for (int c = 0; c < KCHUNKS; ++c) {
        if (c + 3 < KCHUNKS) fill(c + 3);
        cp_commit();
        cp_wait3();
        __syncthreads();

        const uint4*    Af = (const uint4*)(smem + (c & 3) * ASTAGE);
        const uint32_t* Bf = (const uint32_t*)(smem + 4 * ASTAGE + (c & 3) * BSTAGE);
#pragma unroll
        for (int ks = 0; ks < 4; ++ks) {
            uint4 a[4];
#pragma unroll
            for (int mt = 0; mt < 4; ++mt)
                a[mt] = Af[((wm * 4 + mt) * 4 + ks) * 32 + lane];
            uint32_t b[4][2];
#pragma unroll
            for (int nt = 0; nt < 4; ++nt) {
                const int nn = (wn * 32 + nt * 8 + g) * 36 + ks * 8 + tig;
                b[nt][0] = Bf[nn];
                b[nt][1] = Bf[nn + 4];
            }
#pragma unroll
            for (int mt = 0; mt < 4; ++mt)
#pragma unroll
                for (int nt = 0; nt < 4; ++nt)
                    mma_tf32(d[mt][nt][0], d[mt][nt][1], d[mt][nt][2], d[mt][nt][3],
                             a[mt].x, a[mt].y, a[mt].z, a[mt].w, b[nt][0], b[nt][1]);
        }
        __syncthreads();
    }

    // ---------------- epilogue: stage warp tile in smem, coalesced stores ----
    float* S = (float*)smem + wid * 32 * 68;   // [n=32][m=64], stride 68
#pragma unroll
    for (int mt = 0; mt < 4; ++mt)
#pragma unroll
        for (int nt = 0; nt < 4; ++nt) {
            const int mb = mt * 16 + g;
            const int nb = nt * 8 + tig * 2;
            S[(nb + 0) * 68 + mb]     = d[mt][nt][0];
            S[(nb + 1) * 68 + mb]     = d[mt][nt][1];
            S[(nb + 0) * 68 + mb + 8] = d[mt][nt][2];
            S[(nb + 1) * 68 + mb + 8] = d[mt][nt][3];
        }
    __syncwarp();

    const int q    = lane & 15;
    const int half = lane >> 4;
    const int co0  = m0 + wm * 64;
    const int pw0  = p0 + wn * 32;
    const int Cout = args.Cout;
    const int mode = args.mode;

    if (mode == 0) {
        float4 b4 = *(const float4*)(args.bias + co0 + q * 4);
        float* ob = args.outp[l] + (size_t)n * HW * 256;
#pragma unroll 4
        for (int it = 0; it < 16; ++it) {
            const int row = it * 2 + half;
            const int p   = pw0 + row;
            if (p >= HW) continue;
            float4 v = *(const float4*)&S[row * 68 + q * 4];
            v.x = tf32r(fmaxf(v.x + b4.x, 0.f));
            v.y = tf32r(fmaxf(v.y + b4.y, 0.f));
            v.z = tf32r(fmaxf(v.z + b4.z, 0.f));
            v.w = tf32r(fmaxf(v.w + b4.w, 0.f));
            *(float4*)(ob + (size_t)p * 256 + co0 + q * 4) = v;
        }
    } else {
        float bb[4];
        int   cos[4];
#pragma unroll
        for (int e = 0; e < 4; ++e) {
            cos[e] = co0 + q * 4 + e;
            bb[e]  = (cos[e] < Cout) ? __ldg(args.bias + cos[e]) : 0.f;
        }
        float* ob = args.outp[l];
        const size_t nbase = (size_t)n * R_TOTAL + args.row_off[l];
#pragma unroll 2
        for (int it = 0; it < 16; ++it) {
            const int row = it * 2 + half;
            const int p   = pw0 + row;
            if (p >= HW) continue;
            float4 v = *(const float4*)&S[row * 68 + q * 4];
            float vv[4] = {v.x, v.y, v.z, v.w};
#pragma unroll
            for (int e = 0; e < 4; ++e) {
                const int co = cos[e];
                if (co >= Cout) continue;
                if (mode == 1) {
                    const int a  = co / 80;
                    const int kc = co - a * 80;
                    ob[(nbase + (size_t)p * 9 + a) * OUT_C + kc] = vv[e] + bb[e];
                } else {
                    const int a  = co >> 2;
                    const int jb = co & 3;
                    ob[(nbase + (size_t)p * 9 + a) * OUT_C + 80 + jb] = vv[e] + bb[e];
                }
            }
        }
    }
}

// ---------------- host ----------------
static const int HS[5]      = {100, 50, 25, 13, 7};
static const int CUMHW[5]   = {0, 10000, 12500, 13125, 13294};
static const int ROWOFF[5]  = {0, 90000, 112500, 118125, 119646};
static const int TILEOFF[6] = {0, 53, 67, 71, 72, 73};      // 192-px tiles
static const int T32OFF[6]  = {0, 313, 392, 412, 418, 420}; // 32-px tiles (transpose)
// conv order: cls0..3, clsHead, box0..3, boxHead ; m-blocks: 2,2,2,2,6,2,2,2,2,1
static const int MBCUM[11]  = {0, 2, 4, 6, 8, 14, 16, 18, 20, 22, 23};
static const int WSRC[10]   = {5, 7, 9, 11, 21, 13, 15, 17, 19, 23};
static const int WCOUT[10]  = {256, 256, 256, 256, 720, 256, 256, 256, 256, 36};

extern "C" void kernel_launch(void* const* d_in, const int* in_sizes, int n_in,
                              void* d_out, int out_size)
{
    float *bufIn = nullptr, *bufA = nullptr, *bufB = nullptr, *wpk = nullptr;
    cudaGetSymbolAddress((void**)&bufIn, g_bufIn);
    cudaGetSymbolAddress((void**)&bufA,  g_bufA);
    cudaGetSymbolAddress((void**)&bufB,  g_bufB);
    cudaGetSymbolAddress((void**)&wpk,   g_wpack);
    float* out = (float*)d_out;

    cudaFuncSetAttribute(conv_mma_kernel, cudaFuncAttributeMaxDynamicSharedMemorySize, SMEM_BYTES);

    // 1) NCHW -> NHWC (+ tf32 rounding)
    {
        TransArgs ta;
        for (int lv = 0; lv < 5; ++lv) {
            ta.in[lv]  = (const float*)d_in[lv];
            ta.out[lv] = bufIn + (size_t)512 * CUMHW[lv];
            ta.Hs[lv]  = HS[lv];
        }
        for (int i = 0; i < 6; ++i) ta.toff[i] = T32OFF[i];
        nchw2nhwc<<<dim3(420, 8, 2), dim3(32, 8)>>>(ta);
    }

    // 2) weight fragment packing (+ tf32 rounding + row-block zero padding)
    {
        WPArgs wa;
        for (int i = 0; i < 10; ++i) { wa.src[i] = (const float*)d_in[WSRC[i]]; wa.cout[i] = WCOUT[i]; }
        for (int i = 0; i < 11; ++i) wa.mbcum[i] = MBCUM[i];
        wpack_kernel<<<dim3(KCHUNKS, 23), 256>>>(wa, wpk);
    }

    ConvArgs base;
    for (int i = 0; i < 6; ++i) base.tile_off[i] = TILEOFF[i];
    for (int lv = 0; lv < 5; ++lv) {
        base.Hs[lv]      = HS[lv];
        base.row_off[lv] = ROWOFF[lv];
    }
    auto set_in  = [&](ConvArgs& a, float* buf) {
        for (int lv = 0; lv < 5; ++lv) a.in[lv] = buf + (size_t)512 * CUMHW[lv];
    };
    auto set_out = [&](ConvArgs& a, float* buf) {
        for (int lv = 0; lv < 5; ++lv) a.outp[lv] = buf + (size_t)512 * CUMHW[lv];
    };
    auto launch = [&](const ConvArgs& a, int conv) {
        const int mblocks = MBCUM[conv + 1] - MBCUM[conv];
        dim3 grid(TILEOFF[5], mblocks, 2);
        conv_mma_kernel<<<grid, NTHREADS, SMEM_BYTES>>>(a);
    };

    float* bufs[2] = {bufA, bufB};

    for (int tower = 0; tower < 2; ++tower) {
        const int conv0   = (tower == 0) ? 0 : 5;
        const int biasIdx = (tower == 0) ? 6 : 14;   // tower biases stride 2

        for (int i = 0; i < 4; ++i) {
            ConvArgs ai = base;
            ai.Cout = 256; ai.mode = 0;
            ai.wgt  = wpk + (size_t)MBCUM[conv0 + i] * KCHUNKS * 4096;
            ai.bias = (const float*)d_in[biasIdx + 2 * i];
            if (i == 0) set_in(ai, bufIn);
            else        set_in(ai, bufs[(i + 1) & 1]);
            set_out(ai, bufs[i & 1]);
            launch(ai, conv0 + i);
        }

        ConvArgs af = base;
        set_in(af, bufs[1]);
        for (int lv = 0; lv < 5; ++lv) af.outp[lv] = out;
        const int hconv = (tower == 0) ? 4 : 9;
        af.wgt = wpk + (size_t)MBCUM[hconv] * KCHUNKS * 4096;
        if (tower == 0) { af.Cout = 720; af.mode = 1; af.bias = (const float*)d_in[22]; }
        else            { af.Cout = 36;  af.mode = 2; af.bias = (const float*)d_in[24]; }
        launch(af, hconv);
    }
}

// round 14
// speedup vs baseline: 7.3863x; 2.0809x over previous
#include <cuda_runtime.h>
#include <cuda_fp16.h>
#include <cstdint>

#define BM 128
#define BN 192
#define NTHREADS 384
#define R_TOTAL 120087
#define OUT_C 84
#define KCHUNKS 36              // 9 taps * 4 ci-chunks of 64
#define ASTAGE 16384            // 128 m x 64 k x 2B, fragment-packed
#define BSTAGE 27648            // 192 rows x 72 halves (pad) x 2B
#define SMEM_BYTES 176128       // 4*(ASTAGE + BSTAGE)

// ---------------- device scratch ----------------
__device__ __half g_bufIn[6831616];   // NHWC input (2,HW,256) fp16
__device__ __half g_bufA [6831616];
__device__ __half g_bufB [6831616];
__device__ __half g_wpack[6782976];   // 23 row-blocks * 36 chunks * 8192 halves

// ---------------- PTX helpers ----------------
__device__ __forceinline__ uint32_t smem_u32(const void* p) {
    uint32_t a;
    asm("{ .reg .u64 t; cvta.to.shared.u64 t, %1; cvt.u32.u64 %0, t; }" : "=r"(a) : "l"(p));
    return a;
}
__device__ __forceinline__ void cp16_cg(uint32_t dst, const void* src, uint32_t sz) {
    asm volatile("cp.async.cg.shared.global [%0], [%1], 16, %2;" :: "r"(dst), "l"(src), "r"(sz) : "memory");
}
__device__ __forceinline__ void cp_commit() { asm volatile("cp.async.commit_group;" ::: "memory"); }
__device__ __forceinline__ void cp_wait2()  { asm volatile("cp.async.wait_group 2;"  ::: "memory"); }

__device__ __forceinline__ void mma_f16(float& d0, float& d1, float& d2, float& d3,
                                        uint32_t a0, uint32_t a1, uint32_t a2, uint32_t a3,
                                        uint32_t b0, uint32_t b1) {
    asm volatile("mma.sync.aligned.m16n8k16.row.col.f32.f16.f16.f32 "
                 "{%0,%1,%2,%3}, {%4,%5,%6,%7}, {%8,%9}, {%0,%1,%2,%3};"
                 : "+f"(d0), "+f"(d1), "+f"(d2), "+f"(d3)
                 : "r"(a0), "r"(a1), "r"(a2), "r"(a3), "r"(b0), "r"(b1));
}

// ---------------- arg structs ----------------
struct ConvArgs {
    const __half* in[5];     // NHWC level bases [n][p][256] fp16
    void* outp[5];           // __half* NHWC (mode 0) or float* d_out (mode 1/2)
    const __half* wgt;       // fragment-packed weights base for this conv
    const float* bias;
    int row_off[5];
    int Hs[5];
    int tile_off[6];
    int Cout;
    int mode;                // 0 tower(+relu->fp16), 1 cls head, 2 box head
};
struct TransArgs { const float* in[5]; __half* out[5]; int Hs[5]; int toff[6]; };
struct WPArgs { const float* src[10]; int mbcum[11]; int cout[10]; };

// ---------------- prepass: NCHW f32 -> NHWC fp16 ----------------
__global__ void nchw2nhwc(TransArgs a) {
    __shared__ float tile[32][33];
    int t = blockIdx.x;
    int l = 0;
#pragma unroll
    for (int i = 1; i < 5; ++i) l = (t >= a.toff[i]) ? i : l;
    const int HW = a.Hs[l] * a.Hs[l];
    const int p0 = (t - a.toff[l]) * 32;
    const int c0 = blockIdx.y * 32;
    const int n  = blockIdx.z;
    const float* src = a.in[l]  + (size_t)n * 256 * HW;
    __half*      dst = a.out[l] + (size_t)n * HW * 256;
    const int tx = threadIdx.x, ty = threadIdx.y;
#pragma unroll
    for (int i = 0; i < 4; ++i) {
        int cc = ty + 8 * i;
        int p  = p0 + tx;
        tile[cc][tx] = (p < HW) ? src[(size_t)(c0 + cc) * HW + p] : 0.f;
    }
    __syncthreads();
#pragma unroll
    for (int i = 0; i < 4; ++i) {
        int pp = ty + 8 * i;
        int p  = p0 + pp;
        if (p < HW) dst[(size_t)p * 256 + c0 + tx] = __float2half_rn(tile[tx][pp]);
    }
}

// ---------------- prepass: weight fragment packing (fp16, m16n8k16) -------
// src (Cout,256,3,3); k' = tap*256+ci; chunk c covers 64 k': tap=c>>2, ci base (c&3)*64.
// Page 8192 halves: for element (m,k):
//   wm=m>>6, mt=(m>>4)&3, i=(m>>3)&1, g=m&7; ks=k>>4, kk=k&15, j=kk>>3, tig=(kk&7)>>1, e=kk&1
//   idx = (((wm*4+mt)*4+ks)*32 + g*4+tig)*8 + (i+2*j)*2 + e
__global__ void wpack_kernel(WPArgs a, __half* __restrict__ dst) {
    const int c  = blockIdx.x;
    const int rb = blockIdx.y;
    int t = 0;
#pragma unroll
    for (int i = 1; i < 10; ++i) if (rb >= a.mbcum[i]) t = i;
    const int rbl = rb - a.mbcum[t];
    const float* w = a.src[t];
    const int Cout = a.cout[t];
    __half* page = dst + ((size_t)rb * KCHUNKS + c) * 8192;

    for (int idx = threadIdx.x; idx < 8192; idx += 256) {
        const int m = idx >> 6;
        const int k = idx & 63;
        const int co = rbl * 128 + m;
        float v = 0.f;
        if (co < Cout) {
            const int kp  = c * 64 + k;
            const int tap = kp >> 8;
            const int ci  = kp & 255;
            v = w[(size_t)co * 2304 + ci * 9 + tap];
        }
        const int wm = m >> 6, mt = (m >> 4) & 3, i2 = (m >> 3) & 1, g = m & 7;
        const int ks = k >> 4, kk = k & 15, j = kk >> 3, tig = (kk & 7) >> 1, e = kk & 1;
        page[((((wm * 4 + mt) * 4 + ks) * 32 + g * 4 + tig) << 3) + (i2 + 2 * j) * 2 + e] =
            __float2half_rn(v);
    }
}

// ---------------- main fp16 tensor-core conv kernel ----------------
__global__ __launch_bounds__(NTHREADS, 1)
void conv_mma_kernel(ConvArgs args)
{
    extern __shared__ __align__(1024) char smem[];
    const uint32_t sbase = smem_u32(smem);
    const int tid  = threadIdx.x;
    const int wid  = tid >> 5;
    const int lane = tid & 31;
    const int g    = lane >> 2;
    const int tig  = lane & 3;
    const int wm   = wid & 1;     // m half: co [0,64)/[64,128)
    const int wn   = wid >> 1;    // n slice: 0..5 -> px 32-slices

    // level lookup
    const int t = blockIdx.x;
    int l = 0;
#pragma unroll
    for (int i = 1; i < 5; ++i) l = (t >= args.tile_off[i]) ? i : l;
    const int H = args.Hs[l], W = H, HW = H * W;
    const int n  = blockIdx.z;
    const int m0 = blockIdx.y * BM;
    const int p0 = (t - args.tile_off[l]) * BN;
    const __half* in_n  = args.in[l] + (size_t)n * HW * 256;
    const __half* apack = args.wgt + (size_t)blockIdx.y * KCHUNKS * 8192;

    // producer mapping for B: 4 rows per thread (stride 48), 16B chunk tt
    const int rB = tid >> 3;           // 0..47
    const int tt = tid & 7;            // 16B chunk within 128B row
    int py[4], px[4];
    bool pv[4];
#pragma unroll
    for (int j = 0; j < 4; ++j) {
        int p = p0 + rB + 48 * j;
        pv[j] = p < HW;
        py[j] = pv[j] ? p / W : 0;
        px[j] = pv[j] ? p - py[j] * W : 0;
    }

    auto fill = [&](int c) {
        const int st = c & 3;
        const uint32_t abase = sbase + st * ASTAGE;
        const uint32_t bbase = sbase + 4 * ASTAGE + st * BSTAGE;
        // A: linear coalesced copy of fragment-packed page (1024 x 16B)
        const __half* ap = apack + (size_t)c * 8192;
#pragma unroll
        for (int j = 0; j < 3; ++j) {
            const int idx = tid + NTHREADS * j;
            if (idx < 1024) cp16_cg(abase + idx * 16, ap + idx * 8, 16);
        }
        // B: NHWC fp16 gather, 64 channels (8 x 16B per row) with halo zero-fill
        const int slice = c >> 2;
        const int dy = slice / 3 - 1;
        const int dx = slice - (slice / 3) * 3 - 1;
        const int cc = (c & 3) << 6;
#pragma unroll
        for (int j = 0; j < 4; ++j) {
            const int r  = rB + 48 * j;
            const int iy = py[j] + dy, ix = px[j] + dx;
            const bool ok = pv[j] && ((unsigned)iy < (unsigned)H) && ((unsigned)ix < (unsigned)W);
            const __half* bsrc = ok ? (in_n + (((size_t)iy * W + ix) << 8) + cc + tt * 8) : in_n;
            cp16_cg(bbase + r * 144 + tt * 16, bsrc, ok ? 16u : 0u);
        }
    };

    float d[4][4][4];
#pragma unroll
    for (int mt = 0; mt < 4; ++mt)
#pragma unroll
        for (int nt = 0; nt < 4; ++nt)
#pragma unroll
            for (int q = 0; q < 4; ++q) d[mt][nt][q] = 0.f;

    fill(0); cp_commit();
    fill(1); cp_commit();
    fill(2); cp_commit();

    // single-barrier multistage mainloop
    for (int c = 0; c < KCHUNKS; ++c) {
        cp_wait2();
        __syncthreads();

        const uint4*    Af = (const uint4*)(smem + (c & 3) * ASTAGE);
        const uint32_t* Bf = (const uint32_t*)(smem + 4 * ASTAGE + (c & 3) * BSTAGE);
#pragma unroll
        for (int ks = 0; ks < 4; ++ks) {
            uint4 a[4];
#pragma unroll
            for (int mt = 0; mt < 4; ++mt)
                a[mt] = Af[((wm * 4 + mt) * 4 + ks) * 32 + lane];
            uint32_t b[4][2];
#pragma unroll
            for (int nt = 0; nt < 4; ++nt) {
                const int nn = (wn * 32 + nt * 8 + g) * 36 + ks * 8 + tig;
                b[nt][0] = Bf[nn];
                b[nt][1] = Bf[nn + 4];
            }
#pragma unroll
            for (int mt = 0; mt < 4; ++mt)
#pragma unroll
                for (int nt = 0; nt < 4; ++nt)
                    mma_f16(d[mt][nt][0], d[mt][nt][1], d[mt][nt][2], d[mt][nt][3],
                            a[mt].x, a[mt].y, a[mt].z, a[mt].w, b[nt][0], b[nt][1]);
        }

        if (c + 3 < KCHUNKS) fill(c + 3);
        cp_commit();
    }
    __syncthreads();   // protect smem reuse by epilogue staging

    // ---------------- epilogue: stage warp tile in smem, coalesced stores ----
    float* S = (float*)smem + wid * 32 * 68;   // [n=32][m=64], stride 68
#pragma unroll
    for (int mt = 0; mt < 4; ++mt)
#pragma unroll
        for (int nt = 0; nt < 4; ++nt) {
            const int mb = mt * 16 + g;
            const int nb = nt * 8 + tig * 2;
            S[(nb + 0) * 68 + mb]     = d[mt][nt][0];
            S[(nb + 1) * 68 + mb]     = d[mt][nt][1];
            S[(nb + 0) * 68 + mb + 8] = d[mt][nt][2];
            S[(nb + 1) * 68 + mb + 8] = d[mt][nt][3];
        }
    __syncwarp();

    const int q    = lane & 15;
    const int half = lane >> 4;
    const int co0  = m0 + wm * 64;
    const int pw0  = p0 + wn * 32;
    const int Cout = args.Cout;
    const int mode = args.mode;

    if (mode == 0) {
        float4 b4 = *(const float4*)(args.bias + co0 + q * 4);
        __half* ob = (__half*)args.outp[l] + (size_t)n * HW * 256;
#pragma unroll 4
        for (int it = 0; it < 16; ++it) {
            const int row = it * 2 + half;
            const int p   = pw0 + row;
            if (p >= HW) continue;
            float4 v = *(const float4*)&S[row * 68 + q * 4];
            __half2 h0 = __floats2half2_rn(fmaxf(v.x + b4.x, 0.f), fmaxf(v.y + b4.y, 0.f));
            __half2 h1 = __floats2half2_rn(fmaxf(v.z + b4.z, 0.f), fmaxf(v.w + b4.w, 0.f));
            uint2 st;
            st.x = *(uint32_t*)&h0;
            st.y = *(uint32_t*)&h1;
            *(uint2*)(ob + (size_t)p * 256 + co0 + q * 4) = st;
        }
    } else {
        float bb[4];
        int   cos[4];
#pragma unroll
        for (int e = 0; e < 4; ++e) {
            cos[e] = co0 + q * 4 + e;
            bb[e]  = (cos[e] < Cout) ? __ldg(args.bias + cos[e]) : 0.f;
        }
        float* ob = (float*)args.outp[l];
        const size_t nbase = (size_t)n * R_TOTAL + args.row_off[l];
#pragma unroll 2
        for (int it = 0; it < 16; ++it) {
            const int row = it * 2 + half;
            const int p   = pw0 + row;
            if (p >= HW) continue;
            float4 v = *(const float4*)&S[row * 68 + q * 4];
            float vv[4] = {v.x, v.y, v.z, v.w};
#pragma unroll
            for (int e = 0; e < 4; ++e) {
                const int co = cos[e];
                if (co >= Cout) continue;
                if (mode == 1) {
                    const int a  = co / 80;
                    const int kc = co - a * 80;
                    ob[(nbase + (size_t)p * 9 + a) * OUT_C + kc] = vv[e] + bb[e];
                } else {
                    const int a  = co >> 2;
                    const int jb = co & 3;
                    ob[(nbase + (size_t)p * 9 + a) * OUT_C + 80 + jb] = vv[e] + bb[e];
                }
            }
        }
    }
}

// ---------------- host ----------------
static const int HS[5]      = {100, 50, 25, 13, 7};
static const int CUMHW[5]   = {0, 10000, 12500, 13125, 13294};
static const int ROWOFF[5]  = {0, 90000, 112500, 118125, 119646};
static const int TILEOFF[6] = {0, 53, 67, 71, 72, 73};      // 192-px tiles
static const int T32OFF[6]  = {0, 313, 392, 412, 418, 420}; // 32-px tiles (transpose)
// conv order: cls0..3, clsHead, box0..3, boxHead ; m-blocks: 2,2,2,2,6,2,2,2,2,1
static const int MBCUM[11]  = {0, 2, 4, 6, 8, 14, 16, 18, 20, 22, 23};
static const int WSRC[10]   = {5, 7, 9, 11, 21, 13, 15, 17, 19, 23};
static const int WCOUT[10]  = {256, 256, 256, 256, 720, 256, 256, 256, 256, 36};

extern "C" void kernel_launch(void* const* d_in, const int* in_sizes, int n_in,
                              void* d_out, int out_size)
{
    __half *bufIn = nullptr, *bufA = nullptr, *bufB = nullptr, *wpk = nullptr;
    cudaGetSymbolAddress((void**)&bufIn, g_bufIn);
    cudaGetSymbolAddress((void**)&bufA,  g_bufA);
    cudaGetSymbolAddress((void**)&bufB,  g_bufB);
    cudaGetSymbolAddress((void**)&wpk,   g_wpack);
    float* out = (float*)d_out;

    cudaFuncSetAttribute(conv_mma_kernel, cudaFuncAttributeMaxDynamicSharedMemorySize, SMEM_BYTES);

    // 1) NCHW f32 -> NHWC fp16
    {
        TransArgs ta;
        for (int lv = 0; lv < 5; ++lv) {
            ta.in[lv]  = (const float*)d_in[lv];
            ta.out[lv] = bufIn + (size_t)512 * CUMHW[lv];
            ta.Hs[lv]  = HS[lv];
        }
        for (int i = 0; i < 6; ++i) ta.toff[i] = T32OFF[i];
        nchw2nhwc<<<dim3(420, 8, 2), dim3(32, 8)>>>(ta);
    }

    // 2) weight fragment packing (fp16, zero-pad past Cout)
    {
        WPArgs wa;
        for (int i = 0; i < 10; ++i) { wa.src[i] = (const float*)d_in[WSRC[i]]; wa.cout[i] = WCOUT[i]; }
        for (int i = 0; i < 11; ++i) wa.mbcum[i] = MBCUM[i];
        wpack_kernel<<<dim3(KCHUNKS, 23), 256>>>(wa, wpk);
    }

    ConvArgs base;
    for (int i = 0; i < 6; ++i) base.tile_off[i] = TILEOFF[i];
    for (int lv = 0; lv < 5; ++lv) {
        base.Hs[lv]      = HS[lv];
        base.row_off[lv] = ROWOFF[lv];
    }
    auto set_in  = [&](ConvArgs& a, __half* buf) {
        for (int lv = 0; lv < 5; ++lv) a.in[lv] = buf + (size_t)512 * CUMHW[lv];
    };
    auto set_out = [&](ConvArgs& a, __half* buf) {
        for (int lv = 0; lv < 5; ++lv) a.outp[lv] = buf + (size_t)512 * CUMHW[lv];
    };
    auto launch = [&](const ConvArgs& a, int conv) {
        const int mblocks = MBCUM[conv + 1] - MBCUM[conv];
        dim3 grid(TILEOFF[5], mblocks, 2);
        conv_mma_kernel<<<grid, NTHREADS, SMEM_BYTES>>>(a);
    };

    __half* bufs[2] = {bufA, bufB};

    for (int tower = 0; tower < 2; ++tower) {
        const int conv0   = (tower == 0) ? 0 : 5;
        const int biasIdx = (tower == 0) ? 6 : 14;

        for (int i = 0; i < 4; ++i) {
            ConvArgs ai = base;
            ai.Cout = 256; ai.mode = 0;
            ai.wgt  = wpk + (size_t)MBCUM[conv0 + i] * KCHUNKS * 8192;
            ai.bias = (const float*)d_in[biasIdx + 2 * i];
            if (i == 0) set_in(ai, bufIn);
            else        set_in(ai, bufs[(i + 1) & 1]);
            set_out(ai, bufs[i & 1]);
            launch(ai, conv0 + i);
        }

        ConvArgs af = base;
        set_in(af, bufs[1]);
        for (int lv = 0; lv < 5; ++lv) af.outp[lv] = out;
        const int hconv = (tower == 0) ? 4 : 9;
        af.wgt = wpk + (size_t)MBCUM[hconv] * KCHUNKS * 8192;
        if (tower == 0) { af.Cout = 720; af.mode = 1; af.bias = (const float*)d_in[22]; }
        else            { af.Cout = 36;  af.mode = 2; af.bias = (const float*)d_in[24]; }
        launch(af, hconv);
    }
}